// round 2
// baseline (speedup 1.0000x reference)
#include <cuda_runtime.h>
#include <cuda_fp16.h>
#include <mma.h>
#include <cstdint>

using namespace nvcuda;

#define BATCH 256
#define SEQ   256
#define NIN   512
#define HDIM  1024
#define H4    4096
#define MOUT  512
#define NCTA  128
#define PCOLS 32

// ------------ scratch (device globals; allocation-free) ------------
__device__ __half g_x16[(size_t)BATCH * SEQ * NIN];
__device__ __half g_Wx16[(size_t)H4 * NIN];
__device__ __half g_Wh16[(size_t)H4 * HDIM];
__device__ float  g_bx[H4];
__device__ float  g_pre[(size_t)SEQ * BATCH * H4];   // 1 GiB
__device__ float  g_hfin[(size_t)BATCH * HDIM];
__device__ __half g_h16[2][(size_t)BATCH * HDIM];
__device__ unsigned g_barctr;

// ------------ helpers ------------
__device__ __forceinline__ void cp16(void* dst, const void* src) {
    unsigned d = (unsigned)__cvta_generic_to_shared(dst);
    asm volatile("cp.async.cg.shared.global [%0], [%1], 16;\n" :: "r"(d), "l"(src) : "memory");
}
__device__ __forceinline__ void cp_commit() { asm volatile("cp.async.commit_group;\n" ::: "memory"); }
__device__ __forceinline__ void cp_wait1()  { asm volatile("cp.async.wait_group 1;\n" ::: "memory"); }
__device__ __forceinline__ void cp_wait0()  { asm volatile("cp.async.wait_group 0;\n" ::: "memory"); }

__device__ __forceinline__ float sigf(float x)      { return __fdividef(1.f, 1.f + __expf(-x)); }
__device__ __forceinline__ float tanhfast(float x)  { return __fdividef(2.f, 1.f + __expf(-2.f * x)) - 1.f; }

// ------------ prep: convert + gate-interleaved pack + barrier reset ------------
__global__ void prep_kernel(const float* __restrict__ x,
    const float* __restrict__ Wgx, const float* __restrict__ Wix,
    const float* __restrict__ Wfx, const float* __restrict__ Wox,
    const float* __restrict__ Wgh, const float* __restrict__ Wih,
    const float* __restrict__ Wfh, const float* __restrict__ Woh,
    const float* __restrict__ bg,  const float* __restrict__ bi,
    const float* __restrict__ bf,  const float* __restrict__ bo)
{
    size_t t0 = (size_t)blockIdx.x * blockDim.x + threadIdx.x;
    size_t stride = (size_t)gridDim.x * blockDim.x;
    if (t0 == 0) g_barctr = 0u;

    for (size_t i = t0; i < (size_t)BATCH * SEQ * NIN; i += stride)
        g_x16[i] = __float2half_rn(x[i]);

    for (size_t i = t0; i < (size_t)H4 * HDIM; i += stride) {
        int p = (int)(i >> 10), n = (int)(i & 1023);
        int j = p >> 2, g = p & 3;
        const float* W = (g == 0) ? Wgh : (g == 1) ? Wih : (g == 2) ? Wfh : Woh;
        g_Wh16[i] = __float2half_rn(W[(size_t)j * HDIM + n]);
    }
    for (size_t i = t0; i < (size_t)H4 * NIN; i += stride) {
        int p = (int)(i >> 9), n = (int)(i & 511);
        int j = p >> 2, g = p & 3;
        const float* W = (g == 0) ? Wgx : (g == 1) ? Wix : (g == 2) ? Wfx : Wox;
        g_Wx16[i] = __float2half_rn(W[(size_t)j * NIN + n]);
    }
    for (size_t i = t0; i < (size_t)H4; i += stride) {
        int p = (int)i, j = p >> 2, g = p & 3;
        const float* bb = (g == 0) ? bg : (g == 1) ? bi : (g == 2) ? bf : bo;
        g_bx[i] = bb[j];
    }
}

// ------------ PRE GEMM: pre[s][b][p] = sum_n x[b,s,n] * Wx[p,n] ------------
// CTA tile 64 tokens x 64 p-cols, kc=64, double-buffered cp.async, wmma 16x16x16.
__global__ __launch_bounds__(256) void pre_gemm() {
    __shared__ __half As[2][64][72];
    __shared__ __half Bs[2][64][72];
    const int t = threadIdx.x;
    const int warp = t >> 5;
    const int wr = warp & 3;        // 4 row tiles of 16
    const int wc = warp >> 2;       // 2 col tiles of 32
    const int r0 = blockIdx.x * 64; // token tile (b fixed within: 64 | 256)
    const int p0 = blockIdx.y * 64;

    wmma::fragment<wmma::accumulator, 16, 16, 16, float> acc[2];
    wmma::fill_fragment(acc[0], 0.f);
    wmma::fill_fragment(acc[1], 0.f);

    auto loadChunk = [&](int kt, int buf) {
        #pragma unroll
        for (int q = 0; q < 2; q++) {
            int c = t + q * 256;
            int row = c >> 3, cc = c & 7;
            cp16(&As[buf][row][cc * 8], g_x16  + (size_t)(r0 + row) * NIN + kt * 64 + cc * 8);
            cp16(&Bs[buf][row][cc * 8], g_Wx16 + (size_t)(p0 + row) * NIN + kt * 64 + cc * 8);
        }
        cp_commit();
    };

    loadChunk(0, 0);
    for (int kt = 0; kt < 8; kt++) {
        int buf = kt & 1;
        if (kt + 1 < 8) { loadChunk(kt + 1, buf ^ 1); cp_wait1(); }
        else            { cp_wait0(); }
        __syncthreads();
        #pragma unroll
        for (int kk = 0; kk < 4; kk++) {
            wmma::fragment<wmma::matrix_a, 16, 16, 16, __half, wmma::row_major> a;
            wmma::load_matrix_sync(a, &As[buf][wr * 16][kk * 16], 72);
            #pragma unroll
            for (int j = 0; j < 2; j++) {
                wmma::fragment<wmma::matrix_b, 16, 16, 16, __half, wmma::col_major> b;
                wmma::load_matrix_sync(b, &Bs[buf][wc * 32 + j * 16][kk * 16], 72);
                wmma::mma_sync(acc[j], a, b, acc[j]);
            }
        }
        __syncthreads();
    }
    // token r = b*256 + s ; tile rows share b, consecutive rows = consecutive s
    const int bb = r0 >> 8;
    const int s0 = (r0 & 255) + wr * 16;
    #pragma unroll
    for (int j = 0; j < 2; j++) {
        float* ptr = g_pre + ((size_t)s0 * BATCH + bb) * H4 + p0 + wc * 32 + j * 16;
        wmma::store_matrix_sync(ptr, acc[j], (unsigned)(BATCH * H4), wmma::mem_row_major);
    }
}

// ------------ persistent recurrent kernel ------------
// 128 CTAs x 256 thr. CTA owns 32 z-cols (= 8 hidden units, all 4 gates).
// Wh slice SMEM-resident; h streamed per step via cp.async.cg (L1-bypass).
__global__ __launch_bounds__(256) void lstm_kernel() {
    extern __shared__ unsigned char sm[];
    __half* Whs = (__half*)sm;                                  // [32][1024]  64 KB
    __half* hs  = (__half*)(sm + 32 * 1024 * 2);                // [2][64][72] 18 KB
    float*  zs  = (float*)(sm + 32 * 1024 * 2 + 2 * 64 * 72 * 2); // [64][36]  9 KB
    float*  bxs = zs + 64 * 36;                                 // [32]

    const int t = threadIdx.x;
    const int cta = blockIdx.x;
    const int p0 = cta * PCOLS;
    const int warp = t >> 5;
    const int wr = warp >> 1;  // 4 row tiles of 16 (batch)
    const int wc = warp & 1;   // 2 col tiles of 16 (p)

    { // Wh slice resident load (once)
        const uint4* src = (const uint4*)(g_Wh16 + (size_t)p0 * HDIM);
        uint4* dst = (uint4*)Whs;
        for (int i = t; i < 32 * 1024 / 8; i += 256) dst[i] = src[i];
    }
    if (t < PCOLS) bxs[t] = g_bx[p0 + t];
    __syncthreads();

    float c[8];
    #pragma unroll
    for (int j = 0; j < 8; j++) c[j] = 0.f;

    for (int s = 0; s < SEQ; s++) {
        const __half* hsrc = g_h16[s & 1];
        __half* hdst = g_h16[(s + 1) & 1];

        for (int bt = 0; bt < 4; bt++) {
            const int b0 = bt * 64;
            wmma::fragment<wmma::accumulator, 16, 16, 16, float> acc;
            wmma::fill_fragment(acc, 0.f);

            if (s > 0) {
                auto loadH = [&](int kt, int buf) {
                    #pragma unroll
                    for (int q = 0; q < 2; q++) {
                        int cix = t + q * 256;
                        int row = cix >> 3, cc = cix & 7;
                        cp16(hs + buf * (64 * 72) + row * 72 + cc * 8,
                             hsrc + (size_t)(b0 + row) * HDIM + kt * 64 + cc * 8);
                    }
                    cp_commit();
                };
                loadH(0, 0);
                for (int kt = 0; kt < 16; kt++) {
                    int buf = kt & 1;
                    if (kt + 1 < 16) { loadH(kt + 1, buf ^ 1); cp_wait1(); }
                    else             { cp_wait0(); }
                    __syncthreads();
                    #pragma unroll
                    for (int kk = 0; kk < 4; kk++) {
                        wmma::fragment<wmma::matrix_a, 16, 16, 16, __half, wmma::row_major> a;
                        wmma::load_matrix_sync(a, hs + buf * (64 * 72) + (wr * 16) * 72 + kk * 16, 72);
                        wmma::fragment<wmma::matrix_b, 16, 16, 16, __half, wmma::col_major> b;
                        wmma::load_matrix_sync(b, Whs + (wc * 16) * HDIM + kt * 64 + kk * 16, HDIM);
                        wmma::mma_sync(acc, a, b, acc);
                    }
                    __syncthreads();
                }
            }
            wmma::store_matrix_sync(zs + (wr * 16) * 36 + wc * 16, acc, 36, wmma::mem_row_major);
            __syncthreads();

            if (t >= b0 && t < b0 + 64) {   // thread t owns batch row b = t
                const int row = t - b0;
                const float* prer = g_pre + ((size_t)s * BATCH + t) * H4 + p0;
                __align__(16) __half hv[8];
                float hf[8];
                #pragma unroll
                for (int jl = 0; jl < 8; jl++) {
                    float zg = zs[row * 36 + jl * 4 + 0] + prer[jl * 4 + 0] + bxs[jl * 4 + 0];
                    float zi = zs[row * 36 + jl * 4 + 1] + prer[jl * 4 + 1] + bxs[jl * 4 + 1];
                    float zf = zs[row * 36 + jl * 4 + 2] + prer[jl * 4 + 2] + bxs[jl * 4 + 2];
                    float zo = zs[row * 36 + jl * 4 + 3] + prer[jl * 4 + 3] + bxs[jl * 4 + 3];
                    float gg = tanhfast(zg), ii = sigf(zi), ff = sigf(zf), oo = sigf(zo);
                    c[jl] = gg * ii + c[jl] * ff;
                    float hval = tanhfast(c[jl]) * oo;
                    hv[jl] = __float2half_rn(hval);
                    hf[jl] = hval;
                }
                *(uint4*)(hdst + (size_t)t * HDIM + cta * 8) = *(const uint4*)hv;
                if (s == SEQ - 1) {
                    float* fd = g_hfin + (size_t)t * HDIM + cta * 8;
                    #pragma unroll
                    for (int jl = 0; jl < 8; jl++) fd[jl] = hf[jl];
                }
            }
            __syncthreads();
        }

        if (s < SEQ - 1) {  // grid-wide barrier (all 128 CTAs resident)
            __threadfence();
            __syncthreads();
            if (t == 0) {
                atomicAdd(&g_barctr, 1u);
                unsigned target = (unsigned)NCTA * (unsigned)(s + 1);
                volatile unsigned* pv = &g_barctr;
                while (*pv < target) {}
            }
            __syncthreads();
        }
    }
}

// ------------ output GEMM: out[b][m] = hfin[b,:] . Wp[m,:] + bp[m] ------------
__global__ __launch_bounds__(256) void out_gemm(const float* __restrict__ Wp,
                                                const float* __restrict__ bp,
                                                float* __restrict__ out) {
    __shared__ float As[32][33], Bs[32][33];
    const int t = threadIdx.x;
    const int b0 = blockIdx.x * 32, m0 = blockIdx.y * 32;
    const int tr = t >> 4, tc = t & 15;
    float acc[2][2] = {{0.f, 0.f}, {0.f, 0.f}};
    for (int k0 = 0; k0 < HDIM; k0 += 32) {
        #pragma unroll
        for (int q = 0; q < 4; q++) {
            int e = t + q * 256;
            int r = e >> 5, cc = e & 31;
            As[r][cc] = g_hfin[(size_t)(b0 + r) * HDIM + k0 + cc];
            Bs[r][cc] = Wp[(size_t)(m0 + r) * HDIM + k0 + cc];
        }
        __syncthreads();
        #pragma unroll
        for (int k = 0; k < 32; k++) {
            float a0 = As[tr * 2][k], a1 = As[tr * 2 + 1][k];
            float w0 = Bs[tc * 2][k], w1 = Bs[tc * 2 + 1][k];
            acc[0][0] += a0 * w0; acc[0][1] += a0 * w1;
            acc[1][0] += a1 * w0; acc[1][1] += a1 * w1;
        }
        __syncthreads();
    }
    #pragma unroll
    for (int i = 0; i < 2; i++)
        #pragma unroll
        for (int j = 0; j < 2; j++)
            out[(size_t)(b0 + tr * 2 + i) * MOUT + m0 + tc * 2 + j] =
                acc[i][j] + bp[m0 + tc * 2 + j];
}

// ------------ launch ------------
extern "C" void kernel_launch(void* const* d_in, const int* in_sizes, int n_in,
                              void* d_out, int out_size) {
    const float* x   = (const float*)d_in[0];
    const float* Wgx = (const float*)d_in[1];  const float* bg = (const float*)d_in[2];
    const float* Wgh = (const float*)d_in[3];
    const float* Wix = (const float*)d_in[4];  const float* bi = (const float*)d_in[5];
    const float* Wih = (const float*)d_in[6];
    const float* Wfx = (const float*)d_in[7];  const float* bf = (const float*)d_in[8];
    const float* Wfh = (const float*)d_in[9];
    const float* Wox = (const float*)d_in[10]; const float* bo = (const float*)d_in[11];
    const float* Woh = (const float*)d_in[12];
    const float* Wp  = (const float*)d_in[13]; const float* bp = (const float*)d_in[14];
    float* out = (float*)d_out;

    const int SMEM_LSTM = 32 * 1024 * 2 + 2 * 64 * 72 * 2 + 64 * 36 * 4 + 32 * 4; // 93312
    cudaFuncSetAttribute(lstm_kernel, cudaFuncAttributeMaxDynamicSharedMemorySize, SMEM_LSTM);

    prep_kernel<<<1024, 256>>>(x, Wgx, Wix, Wfx, Wox, Wgh, Wih, Wfh, Woh, bg, bi, bf, bo);
    pre_gemm<<<dim3(1024, 64), 256>>>();
    lstm_kernel<<<NCTA, 256, SMEM_LSTM>>>();
    out_gemm<<<dim3(8, 16), 256>>>(Wp, bp, out);
}

// round 3
// speedup vs baseline: 1.7135x; 1.7135x over previous
#include <cuda_runtime.h>
#include <cuda_fp16.h>
#include <mma.h>
#include <cstdint>

using namespace nvcuda;

#define BATCH 256
#define SEQ   256
#define NIN   512
#define HDIM  1024
#define H4    4096
#define MOUT  512
#define NCTA  128
#define PCOLS 32

// ------------ scratch (device globals; allocation-free) ------------
__device__ __half g_x16[(size_t)BATCH * SEQ * NIN];
__device__ __half g_Wx16[(size_t)H4 * NIN];
__device__ __half g_Wh16[(size_t)H4 * HDIM];
__device__ float  g_bx[H4];
__device__ float  g_pre[(size_t)SEQ * BATCH * H4];   // 1 GiB
__device__ float  g_hfin[(size_t)BATCH * HDIM];
__device__ __half g_h16[2][(size_t)BATCH * HDIM];
__device__ unsigned g_barctr;

// ------------ helpers ------------
__device__ __forceinline__ void cp16(void* dst, const void* src) {
    unsigned d = (unsigned)__cvta_generic_to_shared(dst);
    asm volatile("cp.async.cg.shared.global [%0], [%1], 16;\n" :: "r"(d), "l"(src) : "memory");
}
__device__ __forceinline__ void cp_commit() { asm volatile("cp.async.commit_group;\n" ::: "memory"); }
__device__ __forceinline__ void cp_wait1()  { asm volatile("cp.async.wait_group 1;\n" ::: "memory"); }
__device__ __forceinline__ void cp_wait0()  { asm volatile("cp.async.wait_group 0;\n" ::: "memory"); }

__device__ __forceinline__ float sigf(float x)      { return __fdividef(1.f, 1.f + __expf(-x)); }
__device__ __forceinline__ float tanhfast(float x)  { return __fdividef(2.f, 1.f + __expf(-2.f * x)) - 1.f; }

// ------------ prep: convert + gate-interleaved pack + barrier reset ------------
__global__ void prep_kernel(const float* __restrict__ x,
    const float* __restrict__ Wgx, const float* __restrict__ Wix,
    const float* __restrict__ Wfx, const float* __restrict__ Wox,
    const float* __restrict__ Wgh, const float* __restrict__ Wih,
    const float* __restrict__ Wfh, const float* __restrict__ Woh,
    const float* __restrict__ bg,  const float* __restrict__ bi,
    const float* __restrict__ bf,  const float* __restrict__ bo)
{
    size_t t0 = (size_t)blockIdx.x * blockDim.x + threadIdx.x;
    size_t stride = (size_t)gridDim.x * blockDim.x;
    if (t0 == 0) g_barctr = 0u;

    for (size_t i = t0; i < (size_t)BATCH * SEQ * NIN; i += stride)
        g_x16[i] = __float2half_rn(x[i]);

    for (size_t i = t0; i < (size_t)H4 * HDIM; i += stride) {
        int p = (int)(i >> 10), n = (int)(i & 1023);
        int j = p >> 2, g = p & 3;
        const float* W = (g == 0) ? Wgh : (g == 1) ? Wih : (g == 2) ? Wfh : Woh;
        g_Wh16[i] = __float2half_rn(W[(size_t)j * HDIM + n]);
    }
    for (size_t i = t0; i < (size_t)H4 * NIN; i += stride) {
        int p = (int)(i >> 9), n = (int)(i & 511);
        int j = p >> 2, g = p & 3;
        const float* W = (g == 0) ? Wgx : (g == 1) ? Wix : (g == 2) ? Wfx : Wox;
        g_Wx16[i] = __float2half_rn(W[(size_t)j * NIN + n]);
    }
    for (size_t i = t0; i < (size_t)H4; i += stride) {
        int p = (int)i, j = p >> 2, g = p & 3;
        const float* bb = (g == 0) ? bg : (g == 1) ? bi : (g == 2) ? bf : bo;
        g_bx[i] = bb[j];
    }
}

// ------------ PRE GEMM: pre[s][b][p] = sum_n x[b,s,n] * Wx[p,n] ------------
// CTA tile 128 tokens x 64 p-cols; 8 warps, each 32x32 (acc[2][2]); kc=64 double-buffered.
__global__ __launch_bounds__(256) void pre_gemm() {
    extern __shared__ unsigned char smp[];
    __half* As = (__half*)smp;                 // [2][128][72]  36864 B
    __half* Bs = (__half*)(smp + 36864);       // [2][64][72]   18432 B
    const int t = threadIdx.x;
    const int warp = t >> 5;
    const int wr = warp >> 1;       // 4 row tiles of 32
    const int wc = warp & 1;        // 2 col tiles of 32
    const int r0 = blockIdx.x * 128;
    const int p0 = blockIdx.y * 64;

    wmma::fragment<wmma::accumulator, 16, 16, 16, float> acc[2][2];
    #pragma unroll
    for (int i = 0; i < 2; i++)
        #pragma unroll
        for (int j = 0; j < 2; j++) wmma::fill_fragment(acc[i][j], 0.f);

    auto loadChunk = [&](int kt, int buf) {
        #pragma unroll
        for (int q = 0; q < 4; q++) {          // A: 128x64 = 1024 cp16
            int c = t + q * 256;
            int row = c >> 3, cc = c & 7;
            cp16(As + buf * (128 * 72) + row * 72 + cc * 8,
                 g_x16 + (size_t)(r0 + row) * NIN + kt * 64 + cc * 8);
        }
        #pragma unroll
        for (int q = 0; q < 2; q++) {          // B: 64x64 = 512 cp16
            int c = t + q * 256;
            int row = c >> 3, cc = c & 7;
            cp16(Bs + buf * (64 * 72) + row * 72 + cc * 8,
                 g_Wx16 + (size_t)(p0 + row) * NIN + kt * 64 + cc * 8);
        }
        cp_commit();
    };

    loadChunk(0, 0);
    for (int kt = 0; kt < 8; kt++) {
        int buf = kt & 1;
        if (kt + 1 < 8) { loadChunk(kt + 1, buf ^ 1); cp_wait1(); }
        else            { cp_wait0(); }
        __syncthreads();
        #pragma unroll
        for (int kk = 0; kk < 4; kk++) {
            wmma::fragment<wmma::matrix_a, 16, 16, 16, __half, wmma::row_major> a[2];
            wmma::fragment<wmma::matrix_b, 16, 16, 16, __half, wmma::col_major> b[2];
            #pragma unroll
            for (int i = 0; i < 2; i++)
                wmma::load_matrix_sync(a[i], As + buf * (128 * 72) + (wr * 32 + i * 16) * 72 + kk * 16, 72);
            #pragma unroll
            for (int j = 0; j < 2; j++)
                wmma::load_matrix_sync(b[j], Bs + buf * (64 * 72) + (wc * 32 + j * 16) * 72 + kk * 16, 72);
            #pragma unroll
            for (int i = 0; i < 2; i++)
                #pragma unroll
                for (int j = 0; j < 2; j++)
                    wmma::mma_sync(acc[i][j], a[i], b[j], acc[i][j]);
        }
        __syncthreads();
    }
    // token r = b*256 + s; 128-row tile lies within one b; consecutive rows = consecutive s
    const int bb = r0 >> 8;
    const int sbase = (r0 & 255) + wr * 32;
    #pragma unroll
    for (int i = 0; i < 2; i++)
        #pragma unroll
        for (int j = 0; j < 2; j++) {
            float* ptr = g_pre + ((size_t)(sbase + i * 16) * BATCH + bb) * H4 + p0 + wc * 32 + j * 16;
            wmma::store_matrix_sync(ptr, acc[i][j], (unsigned)(BATCH * H4), wmma::mem_row_major);
        }
}

// ------------ persistent recurrent kernel ------------
// 128 CTAs x 256 thr. CTA owns 32 z-cols (= 8 hidden units x 4 gates).
// Wh slice SMEM-resident; per step: full 256-batch z-tile, k-chunks of 64,
// 8 warps each 32x32 (acc[2][2]), 2 syncs per chunk, pre-tile prefetched.
__global__ __launch_bounds__(256) void lstm_kernel() {
    extern __shared__ unsigned char sm[];
    __half* Whs  = (__half*)sm;                          // [32][1024]     65536 B
    __half* hbuf = (__half*)(sm + 65536);                // [2][256][72]   73728 B
    float*  zs   = (float*)hbuf;                         // [256][36] aliases hbuf[0]
    float*  pres = (float*)(sm + 65536 + 73728);         // [256][32]      32768 B
    float*  bxs  = (float*)(sm + 65536 + 73728 + 32768); // [32]

    const int t = threadIdx.x;
    const int cta = blockIdx.x;
    const int p0 = cta * PCOLS;
    const int warp = t >> 5;

    { // Wh slice resident load (once)
        const uint4* src = (const uint4*)(g_Wh16 + (size_t)p0 * HDIM);
        uint4* dst = (uint4*)Whs;
        for (int i = t; i < 32 * 1024 / 8; i += 256) dst[i] = src[i];
    }
    if (t < PCOLS) bxs[t] = g_bx[p0 + t];
    __syncthreads();

    float c[8];
    #pragma unroll
    for (int j = 0; j < 8; j++) c[j] = 0.f;

    for (int s = 0; s < SEQ; s++) {
        const __half* hsrc = g_h16[s & 1];
        __half* hdst = g_h16[(s + 1) & 1];

        // prefetch pre tile [256][32] fp32 for this step (own cp.async group)
        {
            const float* pbase = g_pre + ((size_t)s * BATCH) * H4 + p0;
            #pragma unroll
            for (int q = 0; q < 8; q++) {      // 2048 cp16
                int cix = t + q * 256;
                int row = cix >> 3, cc = cix & 7;
                cp16(pres + row * 32 + cc * 4, pbase + (size_t)row * H4 + cc * 4);
            }
            cp_commit();
        }

        wmma::fragment<wmma::accumulator, 16, 16, 16, float> acc[2][2];
        #pragma unroll
        for (int i = 0; i < 2; i++)
            #pragma unroll
            for (int j = 0; j < 2; j++) wmma::fill_fragment(acc[i][j], 0.f);

        if (s > 0) {
            auto loadH = [&](int kt, int buf) {
                #pragma unroll
                for (int q = 0; q < 8; q++) {  // 256x64 halves = 2048 cp16
                    int cix = t + q * 256;
                    int row = cix >> 3, cc = cix & 7;
                    cp16(hbuf + buf * (256 * 72) + row * 72 + cc * 8,
                         hsrc + (size_t)row * HDIM + kt * 64 + cc * 8);
                }
                cp_commit();
            };
            loadH(0, 0);
            for (int kt = 0; kt < 16; kt++) {
                int buf = kt & 1;
                if (kt + 1 < 16) { loadH(kt + 1, buf ^ 1); cp_wait1(); }
                else             { cp_wait0(); }
                __syncthreads();
                #pragma unroll
                for (int kk = 0; kk < 4; kk++) {
                    wmma::fragment<wmma::matrix_a, 16, 16, 16, __half, wmma::row_major> a[2];
                    wmma::fragment<wmma::matrix_b, 16, 16, 16, __half, wmma::col_major> b[2];
                    #pragma unroll
                    for (int i = 0; i < 2; i++)
                        wmma::load_matrix_sync(a[i], hbuf + buf * (256 * 72) + (warp * 32 + i * 16) * 72 + kk * 16, 72);
                    #pragma unroll
                    for (int j = 0; j < 2; j++)
                        wmma::load_matrix_sync(b[j], Whs + (j * 16) * HDIM + kt * 64 + kk * 16, HDIM);
                    #pragma unroll
                    for (int i = 0; i < 2; i++)
                        #pragma unroll
                        for (int j = 0; j < 2; j++)
                            wmma::mma_sync(acc[i][j], a[i], b[j], acc[i][j]);
                }
                __syncthreads();
            }
        } else {
            cp_wait0();          // pre-tile group
            __syncthreads();
        }

        // stage z into smem (aliases hbuf[0], safe: all warps past final sync)
        #pragma unroll
        for (int i = 0; i < 2; i++)
            #pragma unroll
            for (int j = 0; j < 2; j++)
                wmma::store_matrix_sync(zs + (warp * 32 + i * 16) * 36 + j * 16, acc[i][j], 36, wmma::mem_row_major);
        if (s > 0) { cp_wait0(); }   // ensure pre tile landed
        __syncthreads();

        // elementwise: thread t owns batch row t, 8 hidden units
        {
            __align__(16) __half hv[8];
            float hf[8];
            const float* zr = zs + t * 36;
            const float* pr = pres + t * 32;
            #pragma unroll
            for (int jl = 0; jl < 8; jl++) {
                float zg = zr[jl * 4 + 0] + pr[jl * 4 + 0] + bxs[jl * 4 + 0];
                float zi = zr[jl * 4 + 1] + pr[jl * 4 + 1] + bxs[jl * 4 + 1];
                float zf = zr[jl * 4 + 2] + pr[jl * 4 + 2] + bxs[jl * 4 + 2];
                float zo = zr[jl * 4 + 3] + pr[jl * 4 + 3] + bxs[jl * 4 + 3];
                float gg = tanhfast(zg), ii = sigf(zi), ff = sigf(zf), oo = sigf(zo);
                c[jl] = gg * ii + c[jl] * ff;
                float hval = tanhfast(c[jl]) * oo;
                hv[jl] = __float2half_rn(hval);
                hf[jl] = hval;
            }
            *(uint4*)(hdst + (size_t)t * HDIM + cta * 8) = *(const uint4*)hv;
            if (s == SEQ - 1) {
                float* fd = g_hfin + (size_t)t * HDIM + cta * 8;
                #pragma unroll
                for (int jl = 0; jl < 8; jl++) fd[jl] = hf[jl];
            }
        }

        if (s < SEQ - 1) {  // grid-wide barrier (all 128 CTAs resident)
            __threadfence();
            __syncthreads();
            if (t == 0) {
                atomicAdd(&g_barctr, 1u);
                unsigned target = (unsigned)NCTA * (unsigned)(s + 1);
                volatile unsigned* pv = &g_barctr;
                while (*pv < target) {}
            }
            __syncthreads();
        }
    }
}

// ------------ output GEMM: out[b][m] = hfin[b,:] . Wp[m,:] + bp[m] ------------
__global__ __launch_bounds__(256) void out_gemm(const float* __restrict__ Wp,
                                                const float* __restrict__ bp,
                                                float* __restrict__ out) {
    __shared__ float As[32][33], Bs[32][33];
    const int t = threadIdx.x;
    const int b0 = blockIdx.x * 32, m0 = blockIdx.y * 32;
    const int tr = t >> 4, tc = t & 15;
    float acc[2][2] = {{0.f, 0.f}, {0.f, 0.f}};
    for (int k0 = 0; k0 < HDIM; k0 += 32) {
        #pragma unroll
        for (int q = 0; q < 4; q++) {
            int e = t + q * 256;
            int r = e >> 5, cc = e & 31;
            As[r][cc] = g_hfin[(size_t)(b0 + r) * HDIM + k0 + cc];
            Bs[r][cc] = Wp[(size_t)(m0 + r) * HDIM + k0 + cc];
        }
        __syncthreads();
        #pragma unroll
        for (int k = 0; k < 32; k++) {
            float a0 = As[tr * 2][k], a1 = As[tr * 2 + 1][k];
            float w0 = Bs[tc * 2][k], w1 = Bs[tc * 2 + 1][k];
            acc[0][0] += a0 * w0; acc[0][1] += a0 * w1;
            acc[1][0] += a1 * w0; acc[1][1] += a1 * w1;
        }
        __syncthreads();
    }
    #pragma unroll
    for (int i = 0; i < 2; i++)
        #pragma unroll
        for (int j = 0; j < 2; j++)
            out[(size_t)(b0 + tr * 2 + i) * MOUT + m0 + tc * 2 + j] =
                acc[i][j] + bp[m0 + tc * 2 + j];
}

// ------------ launch ------------
extern "C" void kernel_launch(void* const* d_in, const int* in_sizes, int n_in,
                              void* d_out, int out_size) {
    const float* x   = (const float*)d_in[0];
    const float* Wgx = (const float*)d_in[1];  const float* bg = (const float*)d_in[2];
    const float* Wgh = (const float*)d_in[3];
    const float* Wix = (const float*)d_in[4];  const float* bi = (const float*)d_in[5];
    const float* Wih = (const float*)d_in[6];
    const float* Wfx = (const float*)d_in[7];  const float* bf = (const float*)d_in[8];
    const float* Wfh = (const float*)d_in[9];
    const float* Wox = (const float*)d_in[10]; const float* bo = (const float*)d_in[11];
    const float* Woh = (const float*)d_in[12];
    const float* Wp  = (const float*)d_in[13]; const float* bp = (const float*)d_in[14];
    float* out = (float*)d_out;

    const int SMEM_PRE  = 36864 + 18432;                       // 55296
    const int SMEM_LSTM = 65536 + 73728 + 32768 + 128;         // 172160
    cudaFuncSetAttribute(pre_gemm,   cudaFuncAttributeMaxDynamicSharedMemorySize, SMEM_PRE);
    cudaFuncSetAttribute(lstm_kernel, cudaFuncAttributeMaxDynamicSharedMemorySize, SMEM_LSTM);

    prep_kernel<<<1024, 256>>>(x, Wgx, Wix, Wfx, Wox, Wgh, Wih, Wfh, Woh, bg, bi, bf, bo);
    pre_gemm<<<dim3(512, 64), 256, SMEM_PRE>>>();
    lstm_kernel<<<NCTA, 256, SMEM_LSTM>>>();
    out_gemm<<<dim3(8, 16), 256>>>(Wp, bp, out);
}

// round 6
// speedup vs baseline: 3.5031x; 2.0444x over previous
#include <cuda_runtime.h>
#include <cuda_fp16.h>
#include <mma.h>
#include <cstdint>

using namespace nvcuda;

#define BATCH 256
#define SEQ   256
#define NIN   512
#define HDIM  1024
#define H4    4096
#define MOUT  512
#define NCTA  128

// ------------ scratch (device globals; allocation-free) ------------
__device__ __half g_x16[(size_t)BATCH * SEQ * NIN];
__device__ __half g_Wx16[(size_t)H4 * NIN];
__device__ __half g_Wh16[(size_t)H4 * HDIM];
__device__ float  g_bx[H4];
__device__ float  g_pre[(size_t)SEQ * BATCH * H4];   // 1 GiB
__device__ float  g_hfin[(size_t)BATCH * HDIM];
__device__ __half g_h16[2][(size_t)BATCH * HDIM];
__device__ unsigned g_barctr;

// ------------ helpers ------------
__device__ __forceinline__ void cp16(void* dst, const void* src) {
    unsigned d = (unsigned)__cvta_generic_to_shared(dst);
    asm volatile("cp.async.cg.shared.global [%0], [%1], 16;\n" :: "r"(d), "l"(src) : "memory");
}
__device__ __forceinline__ void cp_commit() { asm volatile("cp.async.commit_group;\n" ::: "memory"); }
__device__ __forceinline__ void cp_wait1()  { asm volatile("cp.async.wait_group 1;\n" ::: "memory"); }
__device__ __forceinline__ void cp_wait0()  { asm volatile("cp.async.wait_group 0;\n" ::: "memory"); }

__device__ __forceinline__ float sigf(float x)      { return __fdividef(1.f, 1.f + __expf(-x)); }
__device__ __forceinline__ float tanhfast(float x)  { return __fdividef(2.f, 1.f + __expf(-2.f * x)) - 1.f; }

// ------------ prep: convert + gate-interleaved pack + barrier reset ------------
__global__ void prep_kernel(const float* __restrict__ x,
    const float* __restrict__ Wgx, const float* __restrict__ Wix,
    const float* __restrict__ Wfx, const float* __restrict__ Wox,
    const float* __restrict__ Wgh, const float* __restrict__ Wih,
    const float* __restrict__ Wfh, const float* __restrict__ Woh,
    const float* __restrict__ bg,  const float* __restrict__ bi,
    const float* __restrict__ bf,  const float* __restrict__ bo)
{
    size_t t0 = (size_t)blockIdx.x * blockDim.x + threadIdx.x;
    size_t stride = (size_t)gridDim.x * blockDim.x;
    if (t0 == 0) g_barctr = 0u;

    for (size_t i = t0; i < (size_t)BATCH * SEQ * NIN; i += stride)
        g_x16[i] = __float2half_rn(x[i]);

    for (size_t i = t0; i < (size_t)H4 * HDIM; i += stride) {
        int p = (int)(i >> 10), n = (int)(i & 1023);
        int j = p >> 2, g = p & 3;
        const float* W = (g == 0) ? Wgh : (g == 1) ? Wih : (g == 2) ? Wfh : Woh;
        g_Wh16[i] = __float2half_rn(W[(size_t)j * HDIM + n]);
    }
    for (size_t i = t0; i < (size_t)H4 * NIN; i += stride) {
        int p = (int)(i >> 9), n = (int)(i & 511);
        int j = p >> 2, g = p & 3;
        const float* W = (g == 0) ? Wgx : (g == 1) ? Wix : (g == 2) ? Wfx : Wox;
        g_Wx16[i] = __float2half_rn(W[(size_t)j * NIN + n]);
    }
    for (size_t i = t0; i < (size_t)H4; i += stride) {
        int p = (int)i, j = p >> 2, g = p & 3;
        const float* bb = (g == 0) ? bg : (g == 1) ? bi : (g == 2) ? bf : bo;
        g_bx[i] = bb[j];
    }
}

// ------------ PRE GEMM (unchanged, proven) ------------
__global__ __launch_bounds__(256) void pre_gemm() {
    extern __shared__ unsigned char smp[];
    __half* As = (__half*)smp;                 // [2][128][72]
    __half* Bs = (__half*)(smp + 36864);       // [2][64][72]
    const int t = threadIdx.x;
    const int warp = t >> 5;
    const int wr = warp >> 1;
    const int wc = warp & 1;
    const int r0 = blockIdx.x * 128;
    const int p0 = blockIdx.y * 64;

    wmma::fragment<wmma::accumulator, 16, 16, 16, float> acc[2][2];
    #pragma unroll
    for (int i = 0; i < 2; i++)
        #pragma unroll
        for (int j = 0; j < 2; j++) wmma::fill_fragment(acc[i][j], 0.f);

    auto loadChunk = [&](int kt, int buf) {
        #pragma unroll
        for (int q = 0; q < 4; q++) {
            int c = t + q * 256;
            int row = c >> 3, cc = c & 7;
            cp16(As + buf * (128 * 72) + row * 72 + cc * 8,
                 g_x16 + (size_t)(r0 + row) * NIN + kt * 64 + cc * 8);
        }
        #pragma unroll
        for (int q = 0; q < 2; q++) {
            int c = t + q * 256;
            int row = c >> 3, cc = c & 7;
            cp16(Bs + buf * (64 * 72) + row * 72 + cc * 8,
                 g_Wx16 + (size_t)(p0 + row) * NIN + kt * 64 + cc * 8);
        }
        cp_commit();
    };

    loadChunk(0, 0);
    for (int kt = 0; kt < 8; kt++) {
        int buf = kt & 1;
        if (kt + 1 < 8) { loadChunk(kt + 1, buf ^ 1); cp_wait1(); }
        else            { cp_wait0(); }
        __syncthreads();
        #pragma unroll
        for (int kk = 0; kk < 4; kk++) {
            wmma::fragment<wmma::matrix_a, 16, 16, 16, __half, wmma::row_major> a[2];
            wmma::fragment<wmma::matrix_b, 16, 16, 16, __half, wmma::col_major> b[2];
            #pragma unroll
            for (int i = 0; i < 2; i++)
                wmma::load_matrix_sync(a[i], As + buf * (128 * 72) + (wr * 32 + i * 16) * 72 + kk * 16, 72);
            #pragma unroll
            for (int j = 0; j < 2; j++)
                wmma::load_matrix_sync(b[j], Bs + buf * (64 * 72) + (wc * 32 + j * 16) * 72 + kk * 16, 72);
            #pragma unroll
            for (int i = 0; i < 2; i++)
                #pragma unroll
                for (int j = 0; j < 2; j++)
                    wmma::mma_sync(acc[i][j], a[i], b[j], acc[i][j]);
        }
        __syncthreads();
    }
    const int bb = r0 >> 8;
    const int sbase = (r0 & 255) + wr * 32;
    #pragma unroll
    for (int i = 0; i < 2; i++)
        #pragma unroll
        for (int j = 0; j < 2; j++) {
            float* ptr = g_pre + ((size_t)(sbase + i * 16) * BATCH + bb) * H4 + p0 + wc * 32 + j * 16;
            wmma::store_matrix_sync(ptr, acc[i][j], (unsigned)(BATCH * H4), wmma::mem_row_major);
        }
}

// ------------ persistent recurrent kernel (mma.sync, batch-split) ------------
// 128 CTAs = 64 p-groups x 2 batch-halves. CTA computes z[128 rows][64 p-cols]:
//   rows  = batch b0..b0+127   (b0 = (cta&1)*128)
//   cols  = packed gates p0..p0+63 (p0 = (cta>>1)*64 = 16 hidden units)
// Wh slice SMEM-resident in conflict-free blocked layout [16 kt][64 p][72].
// h chunk [128][64] double-buffered via cp.async; pre tile prefetched.
// smem (halves unless noted):
//   WHS  @ 0      : 16*64*72*2       = 147456
//   HBUF @ 147456 : 2*128*72*2       =  36864   (zs [128][68] f32 aliases this)
//   PRES @ 184320 : 128*68*4         =  34816   (stride 68 floats, conflict-pad)
//   BXS  @ 219136 : 64*4             =    256
#define OFF_WHS   0
#define OFF_HBUF  147456
#define OFF_PRES  184320
#define OFF_BXS   219136
#define SMEM_LSTM 219392

__global__ __launch_bounds__(256) void lstm_kernel() {
    extern __shared__ __align__(16) unsigned char sm[];
    __half* whs  = (__half*)(sm + OFF_WHS);     // [kt][p][72]
    __half* hbh  = (__half*)(sm + OFF_HBUF);    // [2][128][72]
    float*  zs   = (float*)(sm + OFF_HBUF);     // [128][68] aliases hbuf
    float*  pres = (float*)(sm + OFF_PRES);     // [128][68]
    float*  bxs  = (float*)(sm + OFF_BXS);      // [64]

    const int t = threadIdx.x;
    const int cta = blockIdx.x;
    const int pg  = cta >> 1;          // p-group 0..63
    const int bh  = cta & 1;           // batch half
    const int p0  = pg * 64;
    const int b0  = bh * 128;
    const int warp = t >> 5;
    const int wr = warp >> 1;          // 4 row tiles of 32 (batch rows)
    const int wc = warp & 1;           // 2 col tiles of 32 (p cols)

    // Wh slice resident: whs[kt*4608 + p*72 + kc]
    for (int i = t; i < 8192; i += 256) {          // 8192 x 16B
        int kt = i >> 9, rem = i & 511;
        int p = rem >> 3, cseg = rem & 7;
        uint4 v = *(const uint4*)(g_Wh16 + (size_t)(p0 + p) * HDIM + kt * 64 + cseg * 8);
        *(uint4*)(whs + kt * 4608 + p * 72 + cseg * 8) = v;
    }
    if (t < 64) bxs[t] = g_bx[p0 + t];
    __syncthreads();

    float c[8];
    #pragma unroll
    for (int j = 0; j < 8; j++) c[j] = 0.f;

    const int row  = t >> 1;           // elementwise: batch row within half
    const int half = t & 1;            // 8-unit group within the 16 units

    for (int s = 0; s < SEQ; s++) {
        const __half* hsrc = g_h16[s & 1];
        __half* hdst = g_h16[(s + 1) & 1];

        // prefetch pre tile [128][64] fp32 (joins first cp group)
        {
            const float* pbase = g_pre + ((size_t)s * BATCH + b0) * H4 + p0;
            #pragma unroll
            for (int q = 0; q < 8; q++) {
                int cix = t + q * 256;
                int r = cix >> 4, cseg = cix & 15;
                cp16(pres + r * 68 + cseg * 4, pbase + (size_t)r * H4 + cseg * 4);
            }
        }

        wmma::fragment<wmma::accumulator, 16, 16, 16, float> acc[2][2];

        if (s > 0) {
            #pragma unroll
            for (int i = 0; i < 2; i++)
                #pragma unroll
                for (int j = 0; j < 2; j++) wmma::fill_fragment(acc[i][j], 0.f);

            auto loadH = [&](int kt, int buf) {
                #pragma unroll
                for (int q = 0; q < 4; q++) {      // 128x64 halves = 1024 x 16B
                    int cix = t + q * 256;
                    int r = cix >> 3, cseg = cix & 7;
                    cp16(hbh + buf * 9216 + r * 72 + cseg * 8,
                         hsrc + (size_t)(b0 + r) * HDIM + kt * 64 + cseg * 8);
                }
                cp_commit();
            };
            loadH(0, 0);                            // group0 = pres + chunk0
            for (int kt = 0; kt < 16; kt++) {
                const int buf = kt & 1;
                if (kt + 1 < 16) { loadH(kt + 1, buf ^ 1); cp_wait1(); }
                else             { cp_wait0(); }
                __syncthreads();
                #pragma unroll
                for (int kk = 0; kk < 4; kk++) {
                    wmma::fragment<wmma::matrix_a, 16, 16, 16, __half, wmma::row_major> a[2];
                    wmma::fragment<wmma::matrix_b, 16, 16, 16, __half, wmma::col_major> b[2];
                    #pragma unroll
                    for (int i = 0; i < 2; i++)
                        wmma::load_matrix_sync(a[i], hbh + buf * 9216 + (wr * 32 + i * 16) * 72 + kk * 16, 72);
                    #pragma unroll
                    for (int j = 0; j < 2; j++)
                        wmma::load_matrix_sync(b[j], whs + kt * 4608 + (wc * 32 + j * 16) * 72 + kk * 16, 72);
                    #pragma unroll
                    for (int i = 0; i < 2; i++)
                        #pragma unroll
                        for (int j = 0; j < 2; j++)
                            wmma::mma_sync(acc[i][j], a[i], b[j], acc[i][j]);
                }
                __syncthreads();
            }
            // stage z into smem (aliases hbuf; all compute past final sync)
            #pragma unroll
            for (int i = 0; i < 2; i++)
                #pragma unroll
                for (int j = 0; j < 2; j++)
                    wmma::store_matrix_sync(zs + (wr * 32 + i * 16) * 68 + wc * 32 + j * 16,
                                            acc[i][j], 68, wmma::mem_row_major);
            cp_wait0();           // pre tile landed
            __syncthreads();
        } else {
            cp_commit();
            cp_wait0();
            __syncthreads();
        }

        // elementwise: thread owns (row, 8 units = half*8..half*8+7)
        {
            __align__(16) __half hv[8];
            float hf[8];
            const int cb = half * 32;
            #pragma unroll
            for (int jl = 0; jl < 8; jl++) {
                float4 zq = (s > 0) ? *(const float4*)(zs + row * 68 + cb + jl * 4)
                                    : make_float4(0.f, 0.f, 0.f, 0.f);
                float4 pq = *(const float4*)(pres + row * 68 + cb + jl * 4);
                float zg = zq.x + pq.x + bxs[cb + jl * 4 + 0];
                float zi = zq.y + pq.y + bxs[cb + jl * 4 + 1];
                float zf = zq.z + pq.z + bxs[cb + jl * 4 + 2];
                float zo = zq.w + pq.w + bxs[cb + jl * 4 + 3];
                float gg = tanhfast(zg), ii = sigf(zi), ff = sigf(zf), oo = sigf(zo);
                c[jl] = gg * ii + c[jl] * ff;
                float hval = tanhfast(c[jl]) * oo;
                hv[jl] = __float2half_rn(hval);
                hf[jl] = hval;
            }
            // hidden units j = pg*16 + half*8 + jl
            *(uint4*)(hdst + (size_t)(b0 + row) * HDIM + pg * 16 + half * 8) = *(const uint4*)hv;
            if (s == SEQ - 1) {
                float* fd = g_hfin + (size_t)(b0 + row) * HDIM + pg * 16 + half * 8;
                #pragma unroll
                for (int jl = 0; jl < 8; jl++) fd[jl] = hf[jl];
            }
        }

        if (s < SEQ - 1) {  // grid-wide barrier (all 128 CTAs resident; bounded spin)
            __threadfence();
            __syncthreads();
            if (t == 0) {
                atomicAdd(&g_barctr, 1u);
                unsigned target = (unsigned)NCTA * (unsigned)(s + 1);
                volatile unsigned* pv = &g_barctr;
                for (long it = 0; it < 400000000L; it++) { if (*pv >= target) break; }
            }
            __syncthreads();
        }
    }
}

// ------------ output GEMM ------------
__global__ __launch_bounds__(256) void out_gemm(const float* __restrict__ Wp,
                                                const float* __restrict__ bp,
                                                float* __restrict__ out) {
    __shared__ float As[32][33], Bs[32][33];
    const int t = threadIdx.x;
    const int b0 = blockIdx.x * 32, m0 = blockIdx.y * 32;
    const int tr = t >> 4, tc = t & 15;
    float acc[2][2] = {{0.f, 0.f}, {0.f, 0.f}};
    for (int k0 = 0; k0 < HDIM; k0 += 32) {
        #pragma unroll
        for (int q = 0; q < 4; q++) {
            int e = t + q * 256;
            int r = e >> 5, cc = e & 31;
            As[r][cc] = g_hfin[(size_t)(b0 + r) * HDIM + k0 + cc];
            Bs[r][cc] = Wp[(size_t)(m0 + r) * HDIM + k0 + cc];
        }
        __syncthreads();
        #pragma unroll
        for (int k = 0; k < 32; k++) {
            float a0 = As[tr * 2][k], a1 = As[tr * 2 + 1][k];
            float w0 = Bs[tc * 2][k], w1 = Bs[tc * 2 + 1][k];
            acc[0][0] += a0 * w0; acc[0][1] += a0 * w1;
            acc[1][0] += a1 * w0; acc[1][1] += a1 * w1;
        }
        __syncthreads();
    }
    #pragma unroll
    for (int i = 0; i < 2; i++)
        #pragma unroll
        for (int j = 0; j < 2; j++)
            out[(size_t)(b0 + tr * 2 + i) * MOUT + m0 + tc * 2 + j] =
                acc[i][j] + bp[m0 + tc * 2 + j];
}

// ------------ launch ------------
extern "C" void kernel_launch(void* const* d_in, const int* in_sizes, int n_in,
                              void* d_out, int out_size) {
    const float* x   = (const float*)d_in[0];
    const float* Wgx = (const float*)d_in[1];  const float* bg = (const float*)d_in[2];
    const float* Wgh = (const float*)d_in[3];
    const float* Wix = (const float*)d_in[4];  const float* bi = (const float*)d_in[5];
    const float* Wih = (const float*)d_in[6];
    const float* Wfx = (const float*)d_in[7];  const float* bf = (const float*)d_in[8];
    const float* Wfh = (const float*)d_in[9];
    const float* Wox = (const float*)d_in[10]; const float* bo = (const float*)d_in[11];
    const float* Woh = (const float*)d_in[12];
    const float* Wp  = (const float*)d_in[13]; const float* bp = (const float*)d_in[14];
    float* out = (float*)d_out;

    const int SMEM_PRE = 36864 + 18432;
    cudaFuncSetAttribute(pre_gemm,    cudaFuncAttributeMaxDynamicSharedMemorySize, SMEM_PRE);
    cudaFuncSetAttribute(lstm_kernel, cudaFuncAttributeMaxDynamicSharedMemorySize, SMEM_LSTM);

    prep_kernel<<<1024, 256>>>(x, Wgx, Wix, Wfx, Wox, Wgh, Wih, Wfh, Woh, bg, bi, bf, bo);
    pre_gemm<<<dim3(512, 64), 256, SMEM_PRE>>>();
    lstm_kernel<<<NCTA, 256, SMEM_LSTM>>>();
    out_gemm<<<dim3(8, 16), 256>>>(Wp, bp, out);
}